// round 1
// baseline (speedup 1.0000x reference)
#include <cuda_runtime.h>

// Problem constants
#define BB 8
#define CC 256
#define NN 16384            // H*W
#define NSPLIT 16
#define KCHUNK (NN / NSPLIT)  // 1024

// ---------------- scratch (static __device__, no allocation) ----------------
__device__ float d_s0[BB * CC];                        // row sums of x0
__device__ float d_s1[BB * CC];                        // row sums of x1
__device__ float d_Mpart[(size_t)NSPLIT * BB * CC * CC];  // split-K partials of x1·x0^T
__device__ float d_M[BB * CC * CC];                    // M[b] = x1[b]·x0[b]^T
__device__ float d_T1[BB * CC * CC];                   // theta_w · M[b]
__device__ float d_fraw[BB * CC * CC];                 // T1 · phi_w^T (pre-correction logits)
__device__ float d_fS[BB * CC * CC];                   // softmax(f) over axis c
__device__ float d_A2[BB * CC * CC];                   // fS[b] · g_w
__device__ float d_tvec[BB * CC];                      // theta_w · s1[b]
__device__ float d_pvec[BB * CC];                      // phi_w  · s0[b]
__device__ float d_cvec[BB * CC];                      // fS[b] · g_b
__device__ float d_yT[(size_t)BB * NN * CC];           // y stored transposed: [b][n][c]

// ---------------- row sums ----------------
__global__ void rowsum_kernel(const float* __restrict__ x0,
                              const float* __restrict__ x1) {
    const float* x = blockIdx.y ? x1 : x0;
    float* s = blockIdx.y ? d_s1 : d_s0;
    int r = blockIdx.x;  // 0 .. BB*CC-1
    const float4* p = (const float4*)(x + (size_t)r * NN);
    float acc = 0.f;
    for (int k = threadIdx.x; k < NN / 4; k += 256) {
        float4 v = p[k];
        acc += v.x + v.y + v.z + v.w;
    }
    __shared__ float red[256];
    red[threadIdx.x] = acc;
    __syncthreads();
    for (int o = 128; o > 0; o >>= 1) {
        if (threadIdx.x < o) red[threadIdx.x] += red[threadIdx.x + o];
        __syncthreads();
    }
    if (threadIdx.x == 0) s[r] = red[0];
}

// ---------------- generic 64x64 SIMT fp32 GEMM ----------------
// C[m,n] = sum_k A[m,k] * B(k,n)   (+ bias[m])
// TRANSB=false: B is [K][N] row-major (natural).  TRANSB=true: B is [N][K] row-major.
// STORET=true : store C transposed (C[n*ldc + m]).
// blockIdx.z decomposed as (bb = z / zS, ss = z % zS) with independent strides.
template <bool TRANSB, bool STORET, bool BIAS>
__global__ __launch_bounds__(256) void gemm64(
    const float* __restrict__ A, int lda,
    const float* __restrict__ Bm, int ldb,
    float* __restrict__ Cm, int ldc,
    int K, const float* __restrict__ bias,
    int zS,
    long aSB, long aSS, long bSB, long bSS, long cSB, long cSS, long biasSB) {
    int z = blockIdx.z;
    int bb = z / zS;
    int ss = z - bb * zS;
    A  += (size_t)bb * aSB + (size_t)ss * aSS;
    Bm += (size_t)bb * bSB + (size_t)ss * bSS;
    Cm += (size_t)bb * cSB + (size_t)ss * cSS;

    int m0 = blockIdx.y * 64;
    int n0 = blockIdx.x * 64;

    __shared__ float As[16][68];
    __shared__ float Bs[16][68];

    int tx = threadIdx.x, ty = threadIdx.y;
    int t = ty * 16 + tx;
    int arow = t >> 2, akq = t & 3;   // "row-contract" load pattern (64 rows x 16 k)
    int bkk = t >> 4, bnq = t & 15;   // "natural" load pattern (16 k x 64 n)

    float acc[4][4] = {};

    for (int kt = 0; kt < K; kt += 16) {
        float4 av = *(const float4*)&A[(size_t)(m0 + arow) * lda + kt + 4 * akq];
        As[4 * akq + 0][arow] = av.x;
        As[4 * akq + 1][arow] = av.y;
        As[4 * akq + 2][arow] = av.z;
        As[4 * akq + 3][arow] = av.w;
        if (TRANSB) {
            float4 bv = *(const float4*)&Bm[(size_t)(n0 + arow) * ldb + kt + 4 * akq];
            Bs[4 * akq + 0][arow] = bv.x;
            Bs[4 * akq + 1][arow] = bv.y;
            Bs[4 * akq + 2][arow] = bv.z;
            Bs[4 * akq + 3][arow] = bv.w;
        } else {
            float4 bv = *(const float4*)&Bm[(size_t)(kt + bkk) * ldb + n0 + 4 * bnq];
            *(float4*)&Bs[bkk][4 * bnq] = bv;
        }
        __syncthreads();
#pragma unroll
        for (int kk = 0; kk < 16; kk++) {
            float a[4], b[4];
            *(float4*)a = *(const float4*)&As[kk][ty * 4];
            *(float4*)b = *(const float4*)&Bs[kk][tx * 4];
#pragma unroll
            for (int i = 0; i < 4; i++)
#pragma unroll
                for (int j = 0; j < 4; j++) acc[i][j] += a[i] * b[j];
        }
        __syncthreads();
    }

    float bsv[4] = {0.f, 0.f, 0.f, 0.f};
    if (BIAS) {
#pragma unroll
        for (int i = 0; i < 4; i++) bsv[i] = bias[(size_t)bb * biasSB + m0 + ty * 4 + i];
    }
    if (!STORET) {
#pragma unroll
        for (int i = 0; i < 4; i++) {
            float4 v = {acc[i][0] + bsv[i], acc[i][1] + bsv[i],
                        acc[i][2] + bsv[i], acc[i][3] + bsv[i]};
            *(float4*)&Cm[(size_t)(m0 + ty * 4 + i) * ldc + n0 + tx * 4] = v;
        }
    } else {
#pragma unroll
        for (int j = 0; j < 4; j++) {
            float4 v = {acc[0][j] + bsv[0], acc[1][j] + bsv[1],
                        acc[2][j] + bsv[2], acc[3][j] + bsv[3]};
            *(float4*)&Cm[(size_t)(n0 + tx * 4 + j) * ldc + m0 + ty * 4] = v;
        }
    }
}

// ---------------- reduce split-K partials of M ----------------
__global__ void reduceM_kernel() {
    int idx = blockIdx.x * 256 + threadIdx.x;  // 0 .. BB*CC*CC-1
    float acc = 0.f;
#pragma unroll
    for (int s = 0; s < NSPLIT; s++)
        acc += d_Mpart[(size_t)s * BB * CC * CC + idx];
    d_M[idx] = acc;
}

// ---------------- tvec/pvec: theta_w·s1, phi_w·s0 ----------------
__global__ void tvpv_kernel(const float* __restrict__ theta_w,
                            const float* __restrict__ phi_w) {
    int b = blockIdx.x;
    int c = threadIdx.x;
    float tv = 0.f, pv = 0.f;
    for (int i = 0; i < CC; i++) {
        tv += theta_w[c * CC + i] * d_s1[b * CC + i];
        pv += phi_w[c * CC + i] * d_s0[b * CC + i];
    }
    d_tvec[b * CC + c] = tv;
    d_pvec[b * CC + c] = pv;
}

// ---------------- softmax over axis c with bias corrections ----------------
// l[c] = fraw[b,c,d] + phi_b[d]*tvec[b,c] + theta_b[c]*(pvec[b,d] + N*phi_b[d])
__global__ void softmax_kernel(const float* __restrict__ theta_b,
                               const float* __restrict__ phi_b) {
    int b = blockIdx.x >> 8;
    int d = blockIdx.x & 255;
    int c = threadIdx.x;
    size_t idx = ((size_t)b * CC + c) * CC + d;
    float l = d_fraw[idx] + phi_b[d] * d_tvec[b * CC + c] +
              theta_b[c] * (d_pvec[b * CC + d] + (float)NN * phi_b[d]);
    __shared__ float red[256];
    __shared__ float sMax, sSum;
    red[c] = l;
    __syncthreads();
    for (int o = 128; o > 0; o >>= 1) {
        if (c < o) red[c] = fmaxf(red[c], red[c + o]);
        __syncthreads();
    }
    if (c == 0) sMax = red[0];
    __syncthreads();
    float e = expf(l - sMax);
    red[c] = e;
    __syncthreads();
    for (int o = 128; o > 0; o >>= 1) {
        if (c < o) red[c] += red[c + o];
        __syncthreads();
    }
    if (c == 0) sSum = red[0];
    __syncthreads();
    d_fS[idx] = e / sSum;
}

// ---------------- cvec = fS[b] · g_b ----------------
__global__ void cvec_kernel(const float* __restrict__ g_b) {
    int b = blockIdx.x;
    int c = threadIdx.x;
    float acc = 0.f;
    const float* row = d_fS + ((size_t)b * CC + c) * CC;
    for (int e = 0; e < CC; e++) acc += row[e] * g_b[e];
    d_cvec[b * CC + c] = acc;
}

// ---------------- launch ----------------
extern "C" void kernel_launch(void* const* d_in, const int* in_sizes, int n_in,
                              void* d_out, int out_size) {
    const float* x0 = (const float*)d_in[0];
    const float* x1 = (const float*)d_in[1];
    const float* g_w = (const float*)d_in[2];
    const float* g_b = (const float*)d_in[3];
    const float* theta_w = (const float*)d_in[4];
    const float* theta_b = (const float*)d_in[5];
    const float* phi_w = (const float*)d_in[6];
    const float* phi_b = (const float*)d_in[7];
    const float* W_w = (const float*)d_in[8];
    const float* W_b = (const float*)d_in[9];
    float* out = (float*)d_out;

    void *pMpart, *pM, *pT1, *pFraw, *pFS, *pA2, *pYT, *pCvec;
    cudaGetSymbolAddress(&pMpart, d_Mpart);
    cudaGetSymbolAddress(&pM, d_M);
    cudaGetSymbolAddress(&pT1, d_T1);
    cudaGetSymbolAddress(&pFraw, d_fraw);
    cudaGetSymbolAddress(&pFS, d_fS);
    cudaGetSymbolAddress(&pA2, d_A2);
    cudaGetSymbolAddress(&pYT, d_yT);
    cudaGetSymbolAddress(&pCvec, d_cvec);

    dim3 blk(16, 16);
    const long CN = (long)CC * NN;   // per-batch activation stride
    const long CCs = (long)CC * CC;  // per-batch [C,C] stride

    // 1) row sums s0, s1
    rowsum_kernel<<<dim3(BB * CC, 2), 256>>>(x0, x1);

    // 2) M_part[s,b] = x1[b, :, chunk_s] · x0[b, :, chunk_s]^T   (split-K)
    gemm64<true, false, false><<<dim3(4, 4, BB * NSPLIT), blk>>>(
        x1, NN, x0, NN, (float*)pMpart, CC, KCHUNK, nullptr,
        NSPLIT, CN, KCHUNK, CN, KCHUNK, CCs, (long)BB * CC * CC, 0);

    // 3) reduce partials -> M
    reduceM_kernel<<<BB * CC * CC / 256, 256>>>();

    // 4) T1[b] = theta_w · M[b]
    gemm64<false, false, false><<<dim3(4, 4, BB), blk>>>(
        theta_w, CC, (const float*)pM, CC, (float*)pT1, CC, CC, nullptr,
        1, 0, 0, CCs, 0, CCs, 0, 0);

    // 5) tvec, pvec
    tvpv_kernel<<<BB, 256>>>(theta_w, phi_w);

    // 6) fraw[b] = T1[b] · phi_w^T
    gemm64<true, false, false><<<dim3(4, 4, BB), blk>>>(
        (const float*)pT1, CC, phi_w, CC, (float*)pFraw, CC, CC, nullptr,
        1, CCs, 0, 0, 0, CCs, 0, 0);

    // 7) softmax over c (with bias correction terms)
    softmax_kernel<<<BB * CC, 256>>>(theta_b, phi_b);

    // 8) A2[b] = fS[b] · g_w
    gemm64<false, false, false><<<dim3(4, 4, BB), blk>>>(
        (const float*)pFS, CC, g_w, CC, (float*)pA2, CC, CC, nullptr,
        1, CCs, 0, 0, 0, CCs, 0, 0);

    // 9) cvec[b] = fS[b] · g_b
    cvec_kernel<<<BB, 256>>>(g_b);

    // 10) yT[b][n][c] = (A2[b] · x0[b])^T + cvec  (stored transposed)
    gemm64<false, true, true><<<dim3(NN / 64, 4, BB), blk>>>(
        (const float*)pA2, CC, x0, NN, (float*)pYT, CC, CC, (const float*)pCvec,
        1, CCs, 0, CN, 0, CN, 0, CC);

    // 11) out[b,o,256u+c] = sum_k W_w[o,k] * yT[b][64k+u][c] + W_b[o]
    gemm64<false, false, true><<<dim3(4, 4, BB * 64), blk>>>(
        W_w, CC, (const float*)pYT, 64 * CC, out, NN, CC, W_b,
        64, 0, 0, CN, CC, CN, CC, 0);
}

// round 3
// speedup vs baseline: 2.8801x; 2.8801x over previous
#include <cuda_runtime.h>
#include <cuda_bf16.h>
#include <cstdint>

#define BB 8
#define CC 256
#define NN 16384
#define NSPLIT 16
static const long CN = (long)CC * NN;

// ---------------- device scratch ----------------
__device__ float d_s0[BB * CC];
__device__ float d_s1[BB * CC];
__device__ float d_Mpart[(size_t)NSPLIT * BB * CC * CC];
__device__ float d_M[BB * CC * CC];
__device__ float d_T1[BB * CC * CC];
__device__ float d_fraw[BB * CC * CC];
__device__ float d_fS[BB * CC * CC];
__device__ float d_A2[BB * CC * CC];
__device__ float d_tvec[BB * CC];
__device__ float d_pvec[BB * CC];
__device__ float d_cvec[BB * CC];
__device__ float d_yT[(size_t)BB * NN * CC];

// ---------------- helpers ----------------
__device__ __forceinline__ void split_pack(float a, float b, uint32_t& hi, uint32_t& lo) {
    __nv_bfloat16 h0 = __float2bfloat16(a);
    __nv_bfloat16 h1 = __float2bfloat16(b);
    __nv_bfloat16 l0 = __float2bfloat16(a - __bfloat162float(h0));
    __nv_bfloat16 l1 = __float2bfloat16(b - __bfloat162float(h1));
    hi = ((uint32_t)__bfloat16_as_ushort(h1) << 16) | __bfloat16_as_ushort(h0);
    lo = ((uint32_t)__bfloat16_as_ushort(l1) << 16) | __bfloat16_as_ushort(l0);
}

__device__ __forceinline__ void mma_bf16(float* c, const uint32_t* a, const uint32_t* b) {
    asm volatile(
        "mma.sync.aligned.m16n8k16.row.col.f32.bf16.bf16.f32 "
        "{%0,%1,%2,%3},{%4,%5,%6,%7},{%8,%9},{%0,%1,%2,%3};"
        : "+f"(c[0]), "+f"(c[1]), "+f"(c[2]), "+f"(c[3])
        : "r"(a[0]), "r"(a[1]), "r"(a[2]), "r"(a[3]), "r"(b[0]), "r"(b[1]));
}

#define BK 32
#define KP 16          // k-pairs per chunk
#define ST 20          // smem row stride in b32 (pad 4) -> conflict-free frags

// ---------------- tensor-core GEMM: C[128m,128n] = A[128,K] * B[128n,K]^T ----------------
// A element [m][k]: ATRANS=0 -> Ap + m*aRS + k ; ATRANS=1 -> Ap + k*aRS + m
// B element [n][k]: BTRANS=0 -> Bp + n*bRS + k ; BTRANS=1 -> Bp + k*bRS + n
// BIAS: 0 none, 1 per-m-row, 2 per-n-col.  SUMS: atomicAdd fp32 row sums (gram only).
template <int ATRANS, int BTRANS, int BIAS, int SUMS>
__global__ __launch_bounds__(256, 2) void tc(
    const float* __restrict__ A, long aB, long aMT, long aS, long aRS,
    const float* __restrict__ B, long bB, long bNT, long bS, long bRS,
    float* __restrict__ C, long cB, long cS, long cMT, long cNT, long cLD,
    const float* __restrict__ bias, long biasB,
    float* __restrict__ sumA, float* __restrict__ sumB,
    int K, int nS, int nMT, int nNT) {
    __shared__ uint32_t sAhi[128 * ST], sAlo[128 * ST];
    __shared__ uint32_t sBhi[128 * ST], sBlo[128 * ST];

    const int tid = threadIdx.x;
    const int lane = tid & 31;
    const int wid = tid >> 5;
    const int wm = wid >> 1;   // 0..3
    const int wn = wid & 1;    // 0..1
    const int g = lane >> 2;   // group row 0..7
    const int t4 = lane & 3;   // 0..3

    int z = blockIdx.x;
    const int nt = z % nNT; z /= nNT;
    const int mt = z % nMT; z /= nMT;
    const int s = z % nS;
    const int b = z / nS;

    const float* Ap = A + (size_t)b * aB + (size_t)mt * aMT + (size_t)s * aS;
    const float* Bp = B + (size_t)b * bB + (size_t)nt * bNT + (size_t)s * bS;
    float* Cp = C + (size_t)b * cB + (size_t)s * cS + (size_t)mt * cMT + (size_t)nt * cNT;

    float acc[2][8][4];
#pragma unroll
    for (int i = 0; i < 2; i++)
#pragma unroll
        for (int j = 0; j < 8; j++)
#pragma unroll
            for (int q = 0; q < 4; q++) acc[i][j][q] = 0.f;

    const int nch = K / BK;
    for (int ch = 0; ch < nch; ch++) {
        const int kt = ch * BK;
        // ---- stage A ----
        if (!ATRANS) {
#pragma unroll
            for (int i = tid; i < 128 * KP; i += 256) {
                int r = i >> 4, cp = i & 15;
                float2 v = *(const float2*)(Ap + (size_t)r * aRS + kt + 2 * cp);
                uint32_t hi, lo;
                split_pack(v.x, v.y, hi, lo);
                sAhi[r * ST + cp] = hi;
                sAlo[r * ST + cp] = lo;
                if (SUMS && nt == 0) {
                    float red = v.x + v.y;
#pragma unroll
                    for (int q = 8; q; q >>= 1) red += __shfl_xor_sync(0xffffffffu, red, q);
                    if ((lane & 15) == 0) atomicAdd(&sumA[(size_t)b * CC + mt * 128 + r], red);
                }
            }
        } else {
#pragma unroll
            for (int i = tid; i < 128 * KP; i += 256) {
                int m = i & 127, cp = i >> 7;
                float v0 = Ap[(size_t)(kt + 2 * cp) * aRS + m];
                float v1 = Ap[(size_t)(kt + 2 * cp + 1) * aRS + m];
                uint32_t hi, lo;
                split_pack(v0, v1, hi, lo);
                sAhi[m * ST + cp] = hi;
                sAlo[m * ST + cp] = lo;
            }
        }
        // ---- stage B ----
        if (!BTRANS) {
#pragma unroll
            for (int i = tid; i < 128 * KP; i += 256) {
                int r = i >> 4, cp = i & 15;
                float2 v = *(const float2*)(Bp + (size_t)r * bRS + kt + 2 * cp);
                uint32_t hi, lo;
                split_pack(v.x, v.y, hi, lo);
                sBhi[r * ST + cp] = hi;
                sBlo[r * ST + cp] = lo;
                if (SUMS && mt == 0) {
                    float red = v.x + v.y;
#pragma unroll
                    for (int q = 8; q; q >>= 1) red += __shfl_xor_sync(0xffffffffu, red, q);
                    if ((lane & 15) == 0) atomicAdd(&sumB[(size_t)b * CC + nt * 128 + r], red);
                }
            }
        } else {
#pragma unroll
            for (int i = tid; i < 128 * KP; i += 256) {
                int n = i & 127, cp = i >> 7;
                float v0 = Bp[(size_t)(kt + 2 * cp) * bRS + n];
                float v1 = Bp[(size_t)(kt + 2 * cp + 1) * bRS + n];
                uint32_t hi, lo;
                split_pack(v0, v1, hi, lo);
                sBhi[n * ST + cp] = hi;
                sBlo[n * ST + cp] = lo;
            }
        }
        __syncthreads();

        // ---- compute: two k16 steps ----
#pragma unroll
        for (int kk = 0; kk < 2; kk++) {
            const int kb = kk * 8;
            uint32_t af[2][2][4];
#pragma unroll
            for (int mi = 0; mi < 2; mi++) {
                int r = wm * 32 + mi * 16 + g;
#pragma unroll
                for (int p = 0; p < 2; p++) {
                    const uint32_t* S = p ? sAlo : sAhi;
                    af[mi][p][0] = S[r * ST + kb + t4];
                    af[mi][p][1] = S[(r + 8) * ST + kb + t4];
                    af[mi][p][2] = S[r * ST + kb + t4 + 4];
                    af[mi][p][3] = S[(r + 8) * ST + kb + t4 + 4];
                }
            }
            uint32_t bf[8][2][2];
#pragma unroll
            for (int ni = 0; ni < 8; ni++) {
                int n = wn * 64 + ni * 8 + g;
#pragma unroll
                for (int p = 0; p < 2; p++) {
                    const uint32_t* S = p ? sBlo : sBhi;
                    bf[ni][p][0] = S[n * ST + kb + t4];
                    bf[ni][p][1] = S[n * ST + kb + t4 + 4];
                }
            }
#pragma unroll
            for (int mi = 0; mi < 2; mi++)
#pragma unroll
                for (int ni = 0; ni < 8; ni++) {
                    mma_bf16(acc[mi][ni], af[mi][0], bf[ni][0]);  // hi*hi
                    mma_bf16(acc[mi][ni], af[mi][0], bf[ni][1]);  // hi*lo
                    mma_bf16(acc[mi][ni], af[mi][1], bf[ni][0]);  // lo*hi
                }
        }
        __syncthreads();
    }

    // ---- epilogue ----
#pragma unroll
    for (int mi = 0; mi < 2; mi++) {
        int r0 = wm * 32 + mi * 16 + g;
        float bm0 = 0.f, bm1 = 0.f;
        if (BIAS == 1) {
            bm0 = bias[(size_t)b * biasB + mt * 128 + r0];
            bm1 = bias[(size_t)b * biasB + mt * 128 + r0 + 8];
        }
#pragma unroll
        for (int ni = 0; ni < 8; ni++) {
            int cn = wn * 64 + ni * 8 + t4 * 2;
            float bc0 = 0.f, bc1 = 0.f;
            if (BIAS == 2) {
                bc0 = bias[(size_t)b * biasB + nt * 128 + cn];
                bc1 = bias[(size_t)b * biasB + nt * 128 + cn + 1];
            }
            float2 v0 = {acc[mi][ni][0] + bm0 + bc0, acc[mi][ni][1] + bm0 + bc1};
            float2 v1 = {acc[mi][ni][2] + bm1 + bc0, acc[mi][ni][3] + bm1 + bc1};
            *(float2*)(Cp + (size_t)r0 * cLD + cn) = v0;
            *(float2*)(Cp + (size_t)(r0 + 8) * cLD + cn) = v1;
        }
    }
}

// ---------------- small kernels ----------------
__global__ void zeroS_kernel() {
    int i = blockIdx.x * 512 + threadIdx.x;
    if (i < BB * CC) { d_s0[i] = 0.f; d_s1[i] = 0.f; }
}
__global__ void reduceM_kernel() {
    int idx = blockIdx.x * 256 + threadIdx.x;
    float acc = 0.f;
#pragma unroll
    for (int s = 0; s < NSPLIT; s++) acc += d_Mpart[(size_t)s * BB * CC * CC + idx];
    d_M[idx] = acc;
}
__global__ void tvpv_kernel(const float* __restrict__ theta_w,
                            const float* __restrict__ phi_w) {
    int b = blockIdx.x;
    int c = threadIdx.x;
    float tv = 0.f, pv = 0.f;
    for (int i = 0; i < CC; i++) {
        tv += theta_w[c * CC + i] * d_s1[b * CC + i];
        pv += phi_w[c * CC + i] * d_s0[b * CC + i];
    }
    d_tvec[b * CC + c] = tv;
    d_pvec[b * CC + c] = pv;
}
__global__ void softmax_kernel(const float* __restrict__ theta_b,
                               const float* __restrict__ phi_b) {
    int b = blockIdx.x >> 8;
    int d = blockIdx.x & 255;
    int c = threadIdx.x;
    size_t idx = ((size_t)b * CC + c) * CC + d;
    float l = d_fraw[idx] + phi_b[d] * d_tvec[b * CC + c] +
              theta_b[c] * (d_pvec[b * CC + d] + (float)NN * phi_b[d]);
    __shared__ float red[256];
    __shared__ float sMax, sSum;
    red[c] = l;
    __syncthreads();
    for (int o = 128; o > 0; o >>= 1) {
        if (c < o) red[c] = fmaxf(red[c], red[c + o]);
        __syncthreads();
    }
    if (c == 0) sMax = red[0];
    __syncthreads();
    float e = expf(l - sMax);
    red[c] = e;
    __syncthreads();
    for (int o = 128; o > 0; o >>= 1) {
        if (c < o) red[c] += red[c + o];
        __syncthreads();
    }
    if (c == 0) sSum = red[0];
    __syncthreads();
    d_fS[idx] = e / sSum;
}
__global__ void cvec_kernel(const float* __restrict__ g_b) {
    int b = blockIdx.x;
    int c = threadIdx.x;
    float acc = 0.f;
    const float* row = d_fS + ((size_t)b * CC + c) * CC;
    for (int e = 0; e < CC; e++) acc += row[e] * g_b[e];
    d_cvec[b * CC + c] = acc;
}

// ---------------- launch ----------------
extern "C" void kernel_launch(void* const* d_in, const int* in_sizes, int n_in,
                              void* d_out, int out_size) {
    const float* x0 = (const float*)d_in[0];
    const float* x1 = (const float*)d_in[1];
    const float* g_w = (const float*)d_in[2];
    const float* g_b = (const float*)d_in[3];
    const float* theta_w = (const float*)d_in[4];
    const float* theta_b = (const float*)d_in[5];
    const float* phi_w = (const float*)d_in[6];
    const float* phi_b = (const float*)d_in[7];
    const float* W_w = (const float*)d_in[8];
    const float* W_b = (const float*)d_in[9];
    float* out = (float*)d_out;

    void *pMpart, *pM, *pT1, *pFraw, *pFS, *pA2, *pYT, *pCvec, *pS0, *pS1;
    cudaGetSymbolAddress(&pMpart, d_Mpart);
    cudaGetSymbolAddress(&pM, d_M);
    cudaGetSymbolAddress(&pT1, d_T1);
    cudaGetSymbolAddress(&pFraw, d_fraw);
    cudaGetSymbolAddress(&pFS, d_fS);
    cudaGetSymbolAddress(&pA2, d_A2);
    cudaGetSymbolAddress(&pYT, d_yT);
    cudaGetSymbolAddress(&pCvec, d_cvec);
    cudaGetSymbolAddress(&pS0, d_s0);
    cudaGetSymbolAddress(&pS1, d_s1);

    const long CCs = (long)CC * CC;  // 65536

    // 0) zero atomically-accumulated row sums
    zeroS_kernel<<<4, 512>>>();

    // 1) Gram split-K: Mpart[s][b] = x1[b,:,chunk] * x0[b,:,chunk]^T, fused row sums
    tc<0, 0, 0, 1><<<2 * 2 * NSPLIT * BB, 256>>>(
        x1, CN, 128L * NN, 1024, NN,
        x0, CN, 128L * NN, 1024, NN,
        (float*)pMpart, CCs, (long)BB * CCs, 32768, 128, 256,
        nullptr, 0, (float*)pS1, (float*)pS0,
        1024, NSPLIT, 2, 2);

    // 2) reduce partials, bias-correction vectors
    reduceM_kernel<<<BB * CC * CC / 256, 256>>>();
    tvpv_kernel<<<BB, 256>>>(theta_w, phi_w);

    // 3) T1[b] = theta_w * M[b]        (B from M[k][n] -> BTRANS)
    tc<0, 1, 0, 0><<<2 * 2 * BB, 256>>>(
        theta_w, 0, 128L * 256, 0, 256,
        (const float*)pM, CCs, 128, 0, 256,
        (float*)pT1, CCs, 0, 32768, 128, 256,
        nullptr, 0, nullptr, nullptr,
        256, 1, 2, 2);

    // 4) fraw[b] = T1[b] * phi_w^T     (phi_w natural [n][k])
    tc<0, 0, 0, 0><<<2 * 2 * BB, 256>>>(
        (const float*)pT1, CCs, 128L * 256, 0, 256,
        phi_w, 0, 128L * 256, 0, 256,
        (float*)pFraw, CCs, 0, 32768, 128, 256,
        nullptr, 0, nullptr, nullptr,
        256, 1, 2, 2);

    // 5) softmax over c (with bias corrections)
    softmax_kernel<<<BB * CC, 256>>>(theta_b, phi_b);

    // 6) A2[b] = fS[b] * g_w           (B from g_w[k][n] -> BTRANS)
    tc<0, 1, 0, 0><<<2 * 2 * BB, 256>>>(
        (const float*)pFS, CCs, 128L * 256, 0, 256,
        g_w, 0, 128, 0, 256,
        (float*)pA2, CCs, 0, 32768, 128, 256,
        nullptr, 0, nullptr, nullptr,
        256, 1, 2, 2);

    // 7) cvec[b] = fS[b] * g_b
    cvec_kernel<<<BB, 256>>>(g_b);

    // 8) yT[b][n][c] = sum_d x0[b][d][n] * A2[b][c][d] + cvec[b][c]
    //    A = x0 transposed (m = spatial), B = A2 natural [c][d]
    tc<1, 0, 2, 0><<<128 * 2 * BB, 256>>>(
        x0, CN, 128, 0, NN,
        (const float*)pA2, CCs, 128L * 256, 0, 256,
        (float*)pYT, (long)NN * CC, 0, 128L * 256, 128, 256,
        (const float*)pCvec, CC, nullptr, nullptr,
        256, 1, 128, 2);

    // 9) out[b][o][q*256+c] = sum_ch W_w[o][ch] * yT[b][ch*64+q][c] + W_b[o]
    //    B element [k=ch][n=c] at yT + b*CN + q*256 + ch*16384 + c  -> BTRANS
    tc<0, 1, 1, 0><<<2 * 2 * 64 * BB, 256>>>(
        W_w, 0, 128L * 256, 0, 256,
        (const float*)pYT, CN, 128, 256, 16384,
        out, CN, 256, 128L * 16384, 128, 16384,
        W_b, 0, nullptr, nullptr,
        256, 64, 2, 2);
}